// round 1
// baseline (speedup 1.0000x reference)
#include <cuda_runtime.h>

typedef unsigned long long u64;

#define D      32
#define KNN    4
#define TILE_F 128

// ---------------- packed f32x2 helpers (sm_103a FFMA2 path) ----------------
__device__ __forceinline__ u64 fma2(u64 a, u64 b, u64 c) {
    u64 r;
    asm("fma.rn.f32x2 %0, %1, %2, %3;" : "=l"(r) : "l"(a), "l"(b), "l"(c));
    return r;
}
__device__ __forceinline__ u64 add2(u64 a, u64 b) {
    u64 r;
    asm("add.rn.f32x2 %0, %1, %2;" : "=l"(r) : "l"(a), "l"(b));
    return r;
}
__device__ __forceinline__ void unpack2(u64 a, float& lo, float& hi) {
    asm("mov.b64 {%0, %1}, %2;" : "=f"(lo), "=f"(hi) : "l"(a));
}

// ---------------- scratch: per-center squared norms ----------------
__device__ float g_cnorm[4096];

__global__ void cnorm_kernel(const float* __restrict__ ctrs, int n_fcns) {
    int f = blockIdx.x * blockDim.x + threadIdx.x;
    if (f < n_fcns) {
        const float4* c4 = (const float4*)(ctrs + (size_t)f * D);
        float s = 0.0f;
#pragma unroll
        for (int j = 0; j < D / 4; j++) {
            float4 q = __ldg(c4 + j);
            s += q.x * q.x + q.y * q.y + q.z * q.z + q.w * q.w;
        }
        g_cnorm[f] = s;
    }
}

// ---------------- main fused kernel: 1 warp = 32 samples ----------------
__global__ __launch_bounds__(32) void pwl_kernel(
    const float* __restrict__ x,
    const float* __restrict__ ctrs,
    const float* __restrict__ wts,
    const float* __restrict__ offs,
    float* __restrict__ y,
    int n_fcns)
{
    __shared__ __align__(16) float s_ctr[TILE_F * D];   // 16 KB center tile
    __shared__ float s_cn[TILE_F];
    __shared__ float s_x[32][D + 1];                    // padded: conflict-free
    __shared__ int   s_idx[32][KNN];

    const int lane = threadIdx.x;
    const int srow = blockIdx.x * 32 + lane;

    // ---- load this lane's x row into registers (packed pairs) + smem ----
    u64 xp[16];
    {
        const ulonglong2* xg = (const ulonglong2*)(x + (size_t)srow * D);
#pragma unroll
        for (int j = 0; j < 8; j++) {
            ulonglong2 q = __ldg(xg + j);
            xp[2 * j]     = q.x;
            xp[2 * j + 1] = q.y;
            float a, b;
            unpack2(q.x, a, b);
            s_x[lane][4 * j + 0] = a;
            s_x[lane][4 * j + 1] = b;
            unpack2(q.y, a, b);
            s_x[lane][4 * j + 2] = a;
            s_x[lane][4 * j + 3] = b;
        }
    }

    // ---- phase A: stream all centers, keep per-lane stable top-4 ----
    float bd0 = 3.4e38f, bd1 = 3.4e38f, bd2 = 3.4e38f, bd3 = 3.4e38f;
    int   bi0 = 0, bi1 = 0, bi2 = 0, bi3 = 0;

    for (int fbase = 0; fbase < n_fcns; fbase += TILE_F) {
        __syncwarp();
        // stage tile of centers (coalesced) + their norms
        {
            const float4* g4  = (const float4*)(ctrs + (size_t)fbase * D);
            float4*       sc4 = (float4*)s_ctr;
#pragma unroll
            for (int i = 0; i < TILE_F * D / 4 / 32; i++)
                sc4[i * 32 + lane] = __ldg(g4 + i * 32 + lane);
#pragma unroll
            for (int i = 0; i < TILE_F / 32; i++)
                s_cn[i * 32 + lane] = g_cnorm[fbase + i * 32 + lane];
        }
        __syncwarp();

#pragma unroll 2
        for (int ff = 0; ff < TILE_F; ff++) {
            const ulonglong2* c2 = (const ulonglong2*)(s_ctr + ff * D);  // 8 entries
            u64 a0 = 0ull, a1 = 0ull, a2 = 0ull, a3 = 0ull;
#pragma unroll
            for (int j = 0; j < 4; j++) {
                ulonglong2 qa = c2[2 * j];
                ulonglong2 qb = c2[2 * j + 1];
                a0 = fma2(xp[4 * j + 0], qa.x, a0);
                a1 = fma2(xp[4 * j + 1], qa.y, a1);
                a2 = fma2(xp[4 * j + 2], qb.x, a2);
                a3 = fma2(xp[4 * j + 3], qb.y, a3);
            }
            a0 = add2(a0, a1);
            a2 = add2(a2, a3);
            a0 = add2(a0, a2);
            float lo, hi;
            unpack2(a0, lo, hi);
            float dot = lo + hi;
            float s = fmaf(-2.0f, dot, s_cn[ff]);   // ranking score (== d2 - ||x||^2)
            int f = fbase + ff;
            if (s < bd3) {
                if (s < bd0) {
                    bd3 = bd2; bi3 = bi2; bd2 = bd1; bi2 = bi1; bd1 = bd0; bi1 = bi0;
                    bd0 = s; bi0 = f;
                } else if (s < bd1) {
                    bd3 = bd2; bi3 = bi2; bd2 = bd1; bi2 = bi1;
                    bd1 = s; bi1 = f;
                } else if (s < bd2) {
                    bd3 = bd2; bi3 = bi2;
                    bd2 = s; bi2 = f;
                } else {
                    bd3 = s; bi3 = f;
                }
            }
        }
    }

    // ---- publish neighbor indices ----
    s_idx[lane][0] = bi0;
    s_idx[lane][1] = bi1;
    s_idx[lane][2] = bi2;
    s_idx[lane][3] = bi3;
    __syncwarp();

    // ---- phase B: warp-cooperative apply, one sample at a time ----
    // lane = (row = lane>>3 in 0..3, e4 = lane&7): lane covers d in {row,row+4,...}
    // and output columns [4*e4, 4*e4+4).
    const int row = lane >> 3;
    const int e4  = lane & 7;
    const float4* offs4 = (const float4*)offs;

    for (int s = 0; s < 32; s++) {
        float4 acc = make_float4(0.f, 0.f, 0.f, 0.f);
#pragma unroll
        for (int t = 0; t < KNN; t++) {
            int f = s_idx[s][t];
            const float4* w4 = (const float4*)(wts + (size_t)f * D * D);
            const float*  cf = ctrs + (size_t)f * D;
#pragma unroll
            for (int dd = 0; dd < 8; dd++) {
                int d = dd * 4 + row;
                float4 w  = __ldg(w4 + d * 8 + e4);
                float  xc = s_x[s][d] - __ldg(cf + d);
                acc.x = fmaf(xc, w.x, acc.x);
                acc.y = fmaf(xc, w.y, acc.y);
                acc.z = fmaf(xc, w.z, acc.z);
                acc.w = fmaf(xc, w.w, acc.w);
            }
        }
        // reduce partial sums across the 4 'row' lanes sharing this e4
#pragma unroll
        for (int off = 8; off < 32; off <<= 1) {
            acc.x += __shfl_xor_sync(0xffffffffu, acc.x, off);
            acc.y += __shfl_xor_sync(0xffffffffu, acc.y, off);
            acc.z += __shfl_xor_sync(0xffffffffu, acc.z, off);
            acc.w += __shfl_xor_sync(0xffffffffu, acc.w, off);
        }
        if (row == 0) {
#pragma unroll
            for (int t = 0; t < KNN; t++) {
                int f = s_idx[s][t];
                float4 ov = __ldg(offs4 + f * 8 + e4);
                acc.x += ov.x; acc.y += ov.y; acc.z += ov.z; acc.w += ov.w;
            }
            ((float4*)(y + (size_t)(blockIdx.x * 32 + s) * D))[e4] = acc;
        }
    }
}

// ---------------- launch ----------------
extern "C" void kernel_launch(void* const* d_in, const int* in_sizes, int n_in,
                              void* d_out, int out_size)
{
    const float* x    = (const float*)d_in[0];
    const float* ctrs = (const float*)d_in[1];
    const float* wts  = (const float*)d_in[2];
    const float* offs = (const float*)d_in[3];
    float* y = (float*)d_out;

    int n_smps = in_sizes[0] / D;
    int n_fcns = in_sizes[1] / D;

    cnorm_kernel<<<(n_fcns + 255) / 256, 256>>>(ctrs, n_fcns);
    pwl_kernel<<<n_smps / 32, 32>>>(x, ctrs, wts, offs, y, n_fcns);
}

// round 2
// speedup vs baseline: 1.3578x; 1.3578x over previous
#include <cuda_runtime.h>

typedef unsigned long long u64;

#define D       32
#define KNN     4
#define WARPS   4
#define TILE_F  64   // centers staged per warp per tile

// ---------------- packed f32x2 helpers (sm_103a FFMA2 path) ----------------
__device__ __forceinline__ u64 fma2(u64 a, u64 b, u64 c) {
    u64 r;
    asm("fma.rn.f32x2 %0, %1, %2, %3;" : "=l"(r) : "l"(a), "l"(b), "l"(c));
    return r;
}
__device__ __forceinline__ u64 add2(u64 a, u64 b) {
    u64 r;
    asm("add.rn.f32x2 %0, %1, %2;" : "=l"(r) : "l"(a), "l"(b));
    return r;
}
__device__ __forceinline__ void unpack2(u64 a, float& lo, float& hi) {
    asm("mov.b64 {%0, %1}, %2;" : "=f"(lo), "=f"(hi) : "l"(a));
}

// ---------------- scratch: per-center squared norms ----------------
__device__ float g_cnorm[4096];

__global__ void cnorm_kernel(const float* __restrict__ ctrs, int n_fcns) {
    int f = blockIdx.x * blockDim.x + threadIdx.x;
    if (f < n_fcns) {
        const float4* c4 = (const float4*)(ctrs + (size_t)f * D);
        float s = 0.0f;
#pragma unroll
        for (int j = 0; j < D / 4; j++) {
            float4 q = __ldg(c4 + j);
            s += q.x * q.x + q.y * q.y + q.z * q.z + q.w * q.w;
        }
        g_cnorm[f] = s;
    }
}

// ---------------- main fused kernel ----------------
// Block = 128 threads = 4 warps, all serving the SAME 32 samples.
// Phase A: warp w scans centers [w*shard, (w+1)*shard) and keeps a per-lane
//          (lane = sample) top-4. Candidates merged via smem.
// Phase B: warp w applies the gathered local-linear models for samples
//          [w*8, w*8+8) warp-cooperatively.
__global__ __launch_bounds__(128) void pwl_kernel(
    const float* __restrict__ x,
    const float* __restrict__ ctrs,
    const float* __restrict__ wts,
    const float* __restrict__ offs,
    float* __restrict__ y,
    int n_fcns)
{
    __shared__ __align__(16) float s_ctr[WARPS][TILE_F * D]; // 4 x 8KB
    __shared__ float s_cn[WARPS][TILE_F];
    __shared__ float s_x[32][D + 1];                         // padded
    __shared__ float s_cd[32][WARPS * KNN];
    __shared__ int   s_ci[32][WARPS * KNN];
    __shared__ int   s_idx[32][KNN];

    const int lane = threadIdx.x & 31;
    const int w    = threadIdx.x >> 5;
    const int srow = blockIdx.x * 32 + lane;

    // ---- load this lane's x row into registers (packed pairs); warp 0 -> smem ----
    u64 xp[16];
    {
        const ulonglong2* xg = (const ulonglong2*)(x + (size_t)srow * D);
#pragma unroll
        for (int j = 0; j < 8; j++) {
            ulonglong2 q = __ldg(xg + j);
            xp[2 * j]     = q.x;
            xp[2 * j + 1] = q.y;
            if (w == 0) {
                float a, b;
                unpack2(q.x, a, b);
                s_x[lane][4 * j + 0] = a;
                s_x[lane][4 * j + 1] = b;
                unpack2(q.y, a, b);
                s_x[lane][4 * j + 2] = a;
                s_x[lane][4 * j + 3] = b;
            }
        }
    }

    // ---- phase A: stream this warp's center shard, per-lane stable top-4 ----
    const int shard  = n_fcns / WARPS;
    const int fstart = w * shard;
    const int fend   = fstart + shard;

    float bd0 = 3.4e38f, bd1 = 3.4e38f, bd2 = 3.4e38f, bd3 = 3.4e38f;
    int   bi0 = 0, bi1 = 0, bi2 = 0, bi3 = 0;

    for (int fbase = fstart; fbase < fend; fbase += TILE_F) {
        __syncwarp();
        {
            const float4* g4  = (const float4*)(ctrs + (size_t)fbase * D);
            float4*       sc4 = (float4*)s_ctr[w];
#pragma unroll
            for (int i = 0; i < TILE_F * D / 4 / 32; i++)
                sc4[i * 32 + lane] = __ldg(g4 + i * 32 + lane);
#pragma unroll
            for (int i = 0; i < TILE_F / 32; i++)
                s_cn[w][i * 32 + lane] = g_cnorm[fbase + i * 32 + lane];
        }
        __syncwarp();

#pragma unroll 2
        for (int ff = 0; ff < TILE_F; ff++) {
            const ulonglong2* c2 = (const ulonglong2*)(s_ctr[w] + ff * D);
            u64 a0 = 0ull, a1 = 0ull, a2 = 0ull, a3 = 0ull;
#pragma unroll
            for (int j = 0; j < 4; j++) {
                ulonglong2 qa = c2[2 * j];
                ulonglong2 qb = c2[2 * j + 1];
                a0 = fma2(xp[4 * j + 0], qa.x, a0);
                a1 = fma2(xp[4 * j + 1], qa.y, a1);
                a2 = fma2(xp[4 * j + 2], qb.x, a2);
                a3 = fma2(xp[4 * j + 3], qb.y, a3);
            }
            a0 = add2(a0, a1);
            a2 = add2(a2, a3);
            a0 = add2(a0, a2);
            float lo, hi;
            unpack2(a0, lo, hi);
            float dot = lo + hi;
            float s = fmaf(-2.0f, dot, s_cn[w][ff]);  // == d2 - ||x||^2 (rank-equiv)
            int f = fbase + ff;
            if (s < bd3) {
                if (s < bd0) {
                    bd3 = bd2; bi3 = bi2; bd2 = bd1; bi2 = bi1; bd1 = bd0; bi1 = bi0;
                    bd0 = s; bi0 = f;
                } else if (s < bd1) {
                    bd3 = bd2; bi3 = bi2; bd2 = bd1; bi2 = bi1;
                    bd1 = s; bi1 = f;
                } else if (s < bd2) {
                    bd3 = bd2; bi3 = bi2;
                    bd2 = s; bi2 = f;
                } else {
                    bd3 = s; bi3 = f;
                }
            }
        }
    }

    // ---- publish candidates, merge 16 -> 4 per sample ----
    s_cd[lane][w * KNN + 0] = bd0;  s_ci[lane][w * KNN + 0] = bi0;
    s_cd[lane][w * KNN + 1] = bd1;  s_ci[lane][w * KNN + 1] = bi1;
    s_cd[lane][w * KNN + 2] = bd2;  s_ci[lane][w * KNN + 2] = bi2;
    s_cd[lane][w * KNN + 3] = bd3;  s_ci[lane][w * KNN + 3] = bi3;
    __syncthreads();

    if (w == 0) {
        // thread `lane` merges candidates for sample `lane`
        float cd[WARPS * KNN];
        int   ci[WARPS * KNN];
#pragma unroll
        for (int j = 0; j < WARPS * KNN; j++) {
            cd[j] = s_cd[lane][j];
            ci[j] = s_ci[lane][j];
        }
#pragma unroll
        for (int t = 0; t < KNN; t++) {
            int best = 0;
#pragma unroll
            for (int j = 1; j < WARPS * KNN; j++) {
                // lexicographic (dist, idx): matches top_k tie-break by lower index
                if (cd[j] < cd[best] || (cd[j] == cd[best] && ci[j] < ci[best]))
                    best = j;
            }
            s_idx[lane][t] = ci[best];
            cd[best] = 3.4e38f;
        }
    }
    __syncthreads();

    // ---- phase B: warp-cooperative apply, 8 samples per warp ----
    // lane = (row = lane>>3 in 0..3, e4 = lane&7): covers d in {row, row+4, ...}
    // and output columns [4*e4, 4*e4+4).
    const int row = lane >> 3;
    const int e4  = lane & 7;
    const float4* offs4 = (const float4*)offs;

    for (int si = 0; si < 8; si++) {
        const int s = w * 8 + si;
        float4 acc = make_float4(0.f, 0.f, 0.f, 0.f);
#pragma unroll
        for (int t = 0; t < KNN; t++) {
            int f = s_idx[s][t];
            const float4* w4 = (const float4*)(wts + (size_t)f * D * D);
            const float*  cf = ctrs + (size_t)f * D;
#pragma unroll
            for (int dd = 0; dd < 8; dd++) {
                int d = dd * 4 + row;
                float4 wv = __ldg(w4 + d * 8 + e4);
                float  xc = s_x[s][d] - __ldg(cf + d);
                acc.x = fmaf(xc, wv.x, acc.x);
                acc.y = fmaf(xc, wv.y, acc.y);
                acc.z = fmaf(xc, wv.z, acc.z);
                acc.w = fmaf(xc, wv.w, acc.w);
            }
        }
#pragma unroll
        for (int off = 8; off < 32; off <<= 1) {
            acc.x += __shfl_xor_sync(0xffffffffu, acc.x, off);
            acc.y += __shfl_xor_sync(0xffffffffu, acc.y, off);
            acc.z += __shfl_xor_sync(0xffffffffu, acc.z, off);
            acc.w += __shfl_xor_sync(0xffffffffu, acc.w, off);
        }
        if (row == 0) {
#pragma unroll
            for (int t = 0; t < KNN; t++) {
                int f = s_idx[s][t];
                float4 ov = __ldg(offs4 + f * 8 + e4);
                acc.x += ov.x; acc.y += ov.y; acc.z += ov.z; acc.w += ov.w;
            }
            ((float4*)(y + (size_t)(blockIdx.x * 32 + s) * D))[e4] = acc;
        }
    }
}

// ---------------- launch ----------------
extern "C" void kernel_launch(void* const* d_in, const int* in_sizes, int n_in,
                              void* d_out, int out_size)
{
    const float* x    = (const float*)d_in[0];
    const float* ctrs = (const float*)d_in[1];
    const float* wts  = (const float*)d_in[2];
    const float* offs = (const float*)d_in[3];
    float* y = (float*)d_out;

    int n_smps = in_sizes[0] / D;
    int n_fcns = in_sizes[1] / D;

    cnorm_kernel<<<(n_fcns + 255) / 256, 256>>>(ctrs, n_fcns);
    pwl_kernel<<<n_smps / 32, 128>>>(x, ctrs, wts, offs, y, n_fcns);
}